// round 9
// baseline (speedup 1.0000x reference)
#include <cuda_runtime.h>
#include <cuda_bf16.h>
#include <stdint.h>
#include <math.h>

#define NROWS 8192
#define DIM   512
#define TILE  128
#define NBLK  (NROWS / TILE)                 // 64
#define NTILES (NBLK * (NBLK + 1) / 2)       // 2080
#define GRID  148
#define KSLAB 64
#define SLABS_PER_TILE (DIM / KSLAB)         // 8
#define ROWPAD 144                           // bytes per smem row (128B data + 16 pad)
#define STAGE_BYTES (256 * ROWPAD)           // A(128 rows) + B(128 rows) = 36864
#define NSTAGE 4
#define SMEM_BYTES (NSTAGE * STAGE_BYTES)    // 147456

// ---------------- device scratch ----------------
__device__ __align__(256) float          g_x [NROWS * DIM];  // normalized fp32
__device__ __align__(256) __nv_bfloat16  g_xh[NROWS * DIM];  // normalized bf16
__device__ unsigned long long            g_best[NROWS];      // packed (orderkey<<32)|idx
__device__ float                         g_log[NROWS];

__device__ __forceinline__ unsigned long long pack_vi(float v, int i) {
    unsigned u = __float_as_uint(v);
    u = (u & 0x80000000u) ? ~u : (u | 0x80000000u);
    return ((unsigned long long)u << 32) | (unsigned)i;
}
__device__ __forceinline__ uint32_t smem_u32(const void* p) {
    uint32_t a;
    asm("{ .reg .u64 t; cvta.to.shared.u64 t, %1; cvt.u32.u64 %0, t; }" : "=r"(a) : "l"(p));
    return a;
}
__device__ __forceinline__ void cpasync16(uint32_t dst, const void* src) {
    asm volatile("cp.async.cg.shared.global [%0], [%1], 16;" :: "r"(dst), "l"(src) : "memory");
}
__device__ __forceinline__ void cp_commit() { asm volatile("cp.async.commit_group;" ::: "memory"); }
__device__ __forceinline__ void ldsm4(uint32_t* r, uint32_t addr) {
    asm volatile("ldmatrix.sync.aligned.m8n8.x4.shared.b16 {%0,%1,%2,%3}, [%4];"
        : "=r"(r[0]), "=r"(r[1]), "=r"(r[2]), "=r"(r[3]) : "r"(addr));
}
__device__ __forceinline__ void mma16816(float* c, const uint32_t* a, const uint32_t* b) {
    asm volatile(
        "mma.sync.aligned.m16n8k16.row.col.f32.bf16.bf16.f32 "
        "{%0,%1,%2,%3}, {%4,%5,%6,%7}, {%8,%9}, {%0,%1,%2,%3};\n"
        : "+f"(c[0]), "+f"(c[1]), "+f"(c[2]), "+f"(c[3])
        : "r"(a[0]), "r"(a[1]), "r"(a[2]), "r"(a[3]), "r"(b[0]), "r"(b[1]));
}

__device__ __forceinline__ void tile_ij(int t, int& Ib, int& Jb) {
    int I = 0;
    while ((I + 1) * (129 - (I + 1)) / 2 <= t) I++;
    int J = I + (t - I * (129 - I) / 2);
    Ib = I * TILE; Jb = J * TILE;
}

// ---------------- 1) normalize rows, reset argmax buffer ----------------
__global__ void norm_kernel(const float* __restrict__ in) {
    int row = blockIdx.x;
    int tid = threadIdx.x;            // 128 threads
    if (tid == 0) g_best[row] = 0ull;
    float4 v = ((const float4*)(in + (size_t)row * DIM))[tid];
    float s = v.x*v.x + v.y*v.y + v.z*v.z + v.w*v.w;
    #pragma unroll
    for (int o = 16; o; o >>= 1) s += __shfl_xor_sync(0xffffffffu, s, o);
    __shared__ float ws[4];
    if ((tid & 31) == 0) ws[tid >> 5] = s;
    __syncthreads();
    float tot = ws[0] + ws[1] + ws[2] + ws[3];
    float inv = 1.0f / fmaxf(sqrtf(tot), 1e-8f);
    float4 o4 = make_float4(v.x*inv, v.y*inv, v.z*inv, v.w*inv);
    ((float4*)(g_x + (size_t)row * DIM))[tid] = o4;
    __nv_bfloat162* hp = (__nv_bfloat162*)(g_xh + (size_t)row * DIM);
    hp[tid*2+0] = __floats2bfloat162_rn(o4.x, o4.y);
    hp[tid*2+1] = __floats2bfloat162_rn(o4.z, o4.w);
}

// ---------------- 2) persistent symmetric tile GEMM + dual argmax ----------------
__device__ __forceinline__ void load_stage(uint32_t smb, int buf, int k0,
                                           int Ibase, int Jbase, int tid) {
    const uint32_t dst0 = smb + (uint32_t)buf * STAGE_BYTES;
    #pragma unroll
    for (int i = 0; i < 8; i++) {
        int id  = tid + i * 256;        // 0..2047
        int row = id >> 3;              // 0..255 (0-127: A rows, 128-255: B rows)
        int kc  = id & 7;               // 16B chunk within 128B k-slab row
        int gr  = (row < 128) ? (Ibase + row) : (Jbase + row - 128);
        cpasync16(dst0 + (uint32_t)row * ROWPAD + (uint32_t)kc * 16u,
                  g_xh + (size_t)gr * DIM + k0 + kc * 8);
    }
}

__global__ __launch_bounds__(256, 1) void tile_kernel() {
    extern __shared__ char smraw[];
    const uint32_t smb = smem_u32(smraw);
    const int tid  = threadIdx.x;
    const int lane = tid & 31, warp = tid >> 5;
    const int wm = warp >> 1, wn = warp & 1;       // 4x2 warp grid, 32x64 per warp
    const int lrow = lane >> 2, lk2 = (lane & 3) * 2;
    const int p = blockIdx.x;

    // tiles p, p+148, ... ; 2080 = 14*148 + 8
    const int nt = (p < (NTILES - 14 * GRID)) ? 15 : 14;
    const int total = nt * SLABS_PER_TILE;

    // (I,J) double-buffer rings (load tile may be 1 ahead of compute tile)
    int ib0, jb0, ib1, jb1;

    // prologue: 3 slabs in flight
    tile_ij(p, ib0, jb0);
    load_stage(smb, 0, 0 * KSLAB, ib0, jb0, tid); cp_commit();
    load_stage(smb, 1, 1 * KSLAB, ib0, jb0, tid); cp_commit();
    load_stage(smb, 2, 2 * KSLAB, ib0, jb0, tid); cp_commit();

    float acc[2][8][4];
    #pragma unroll
    for (int mf = 0; mf < 2; mf++)
        #pragma unroll
        for (int nf = 0; nf < 8; nf++)
            #pragma unroll
            for (int e = 0; e < 4; e++) acc[mf][nf][e] = 0.0f;

    // ldmatrix lane addressing
    const uint32_t a_row  = (uint32_t)(wm * 32 + (lane & 15));
    const uint32_t a_koff = (uint32_t)((lane >> 4) * 16);
    const uint32_t b_row  = (uint32_t)(128 + wn * 64 + (lane & 7) + ((lane & 16) ? 8 : 0));
    const uint32_t b_koff = (uint32_t)(((lane >> 3) & 1) * 16);

    for (int ci = 0; ci < total; ci++) {
        asm volatile("cp.async.wait_group 2;" ::: "memory");
        __syncthreads();

        const int li = ci + 3;
        if (li < total) {
            const int lw = li >> 3;
            if ((li & 7) == 0) {
                if (lw & 1) tile_ij(lw * GRID + p, ib1, jb1);
                else        tile_ij(lw * GRID + p, ib0, jb0);
            }
            const int lI = (lw & 1) ? ib1 : ib0;
            const int lJ = (lw & 1) ? jb1 : jb0;
            load_stage(smb, li & 3, (li & 7) * KSLAB, lI, lJ, tid);
        }
        cp_commit();   // empty commit on tail keeps group arithmetic uniform

        const uint32_t stg = smb + (uint32_t)(ci & 3) * STAGE_BYTES;
        #pragma unroll
        for (int ks = 0; ks < 4; ks++) {
            uint32_t a[2][4], b[4][4];
            #pragma unroll
            for (int mf = 0; mf < 2; mf++)
                ldsm4(a[mf], stg + (a_row + (uint32_t)mf * 16) * ROWPAD + (uint32_t)ks * 32 + a_koff);
            #pragma unroll
            for (int pp = 0; pp < 4; pp++)
                ldsm4(b[pp], stg + (b_row + (uint32_t)pp * 16) * ROWPAD + (uint32_t)ks * 32 + b_koff);
            #pragma unroll
            for (int mf = 0; mf < 2; mf++)
                #pragma unroll
                for (int pp = 0; pp < 4; pp++) {
                    mma16816(acc[mf][2*pp],     a[mf], &b[pp][0]);
                    mma16816(acc[mf][2*pp + 1], a[mf], &b[pp][2]);
                }
        }

        if ((ci & 7) == 7) {
            const int cw = ci >> 3;
            const int Ibase = (cw & 1) ? ib1 : ib0;
            const int Jbase = (cw & 1) ? jb1 : jb0;

            // ---- row argmax: rows of block I over cols of block J ----
            #pragma unroll
            for (int mf = 0; mf < 2; mf++)
                #pragma unroll
                for (int h = 0; h < 2; h++) {
                    const int gr = Ibase + wm*32 + mf*16 + lrow + h*8;
                    float bv = -1e30f; int bi = 0;
                    #pragma unroll
                    for (int nf = 0; nf < 8; nf++) {
                        const int gc = Jbase + wn*64 + nf*8 + lk2;
                        const float v0 = acc[mf][nf][h*2+0];
                        const float v1 = acc[mf][nf][h*2+1];
                        if (gc     != gr && v0 > bv) { bv = v0; bi = gc;     }
                        if (gc + 1 != gr && v1 > bv) { bv = v1; bi = gc + 1; }
                    }
                    #pragma unroll
                    for (int o = 1; o < 4; o <<= 1) {
                        float ov = __shfl_xor_sync(0xffffffffu, bv, o);
                        int   oi = __shfl_xor_sync(0xffffffffu, bi, o);
                        if (ov > bv) { bv = ov; bi = oi; }
                    }
                    if ((lane & 3) == 0) atomicMax(&g_best[gr], pack_vi(bv, bi));
                }

            // ---- col argmax (symmetry): rows of block J over cols of block I ----
            if (Ibase != Jbase) {
                #pragma unroll
                for (int nf = 0; nf < 8; nf++)
                    #pragma unroll
                    for (int e = 0; e < 2; e++) {
                        const int gc = Jbase + wn*64 + nf*8 + lk2 + e;
                        float bv = -1e30f; int bi = 0;
                        #pragma unroll
                        for (int mf = 0; mf < 2; mf++)
                            #pragma unroll
                            for (int h = 0; h < 2; h++) {
                                const float v = acc[mf][nf][h*2+e];
                                if (v > bv) { bv = v; bi = Ibase + wm*32 + mf*16 + lrow + h*8; }
                            }
                        #pragma unroll
                        for (int o = 4; o < 32; o <<= 1) {
                            float ov = __shfl_xor_sync(0xffffffffu, bv, o);
                            int   oi = __shfl_xor_sync(0xffffffffu, bi, o);
                            if (ov > bv) { bv = ov; bi = oi; }
                        }
                        if (lane < 4) atomicMax(&g_best[gc], pack_vi(bv, bi));
                    }
            }

            #pragma unroll
            for (int mf = 0; mf < 2; mf++)
                #pragma unroll
                for (int nf = 0; nf < 8; nf++)
                    #pragma unroll
                    for (int e = 0; e < 4; e++) acc[mf][nf][e] = 0.0f;
        }
    }
}

// ---------------- 3) per-row NN distance (fp32 exact) ----------------
__global__ void dist_kernel() {
    int row = blockIdx.x;
    int tid = threadIdx.x;   // 128 threads
    int j = (int)(g_best[row] & 0xffffffffull);
    float4 a = ((const float4*)(g_x + (size_t)row * DIM))[tid];
    float4 b = ((const float4*)(g_x + (size_t)j   * DIM))[tid];
    float dx = a.x - b.x + 1e-8f;
    float dy = a.y - b.y + 1e-8f;
    float dz = a.z - b.z + 1e-8f;
    float dw = a.w - b.w + 1e-8f;
    float s = dx*dx + dy*dy + dz*dz + dw*dw;
    #pragma unroll
    for (int o = 16; o; o >>= 1) s += __shfl_xor_sync(0xffffffffu, s, o);
    __shared__ float ws[4];
    if ((tid & 31) == 0) ws[tid >> 5] = s;
    __syncthreads();
    if (tid == 0) {
        float tot = ws[0] + ws[1] + ws[2] + ws[3];
        g_log[row] = logf(sqrtf(tot) + 1e-8f);
    }
}

// ---------------- 4) deterministic final reduce ----------------
__global__ void reduce_kernel(float* __restrict__ out) {
    int tid = threadIdx.x;   // 1024 threads
    float s = 0.0f;
    #pragma unroll
    for (int i = 0; i < NROWS / 1024; i++) s += g_log[tid + i * 1024];
    #pragma unroll
    for (int o = 16; o; o >>= 1) s += __shfl_xor_sync(0xffffffffu, s, o);
    __shared__ float ws[32];
    if ((tid & 31) == 0) ws[tid >> 5] = s;
    __syncthreads();
    if (tid < 32) {
        float v = ws[tid];
        #pragma unroll
        for (int o = 16; o; o >>= 1) v += __shfl_xor_sync(0xffffffffu, v, o);
        if (tid == 0) out[0] = -v / (float)NROWS;
    }
}

extern "C" void kernel_launch(void* const* d_in, const int* in_sizes, int n_in,
                              void* d_out, int out_size) {
    const float* in = (const float*)d_in[0];
    float* out = (float*)d_out;
    (void)in_sizes; (void)n_in; (void)out_size;

    cudaFuncSetAttribute((const void*)tile_kernel,
                         cudaFuncAttributeMaxDynamicSharedMemorySize, SMEM_BYTES);

    norm_kernel<<<NROWS, 128>>>(in);
    tile_kernel<<<GRID, 256, SMEM_BYTES>>>();
    dist_kernel<<<NROWS, 128>>>();
    reduce_kernel<<<1, 1024>>>(out);
}

// round 10
// speedup vs baseline: 1.5274x; 1.5274x over previous
#include <cuda_runtime.h>
#include <cuda_bf16.h>
#include <stdint.h>
#include <math.h>

#define NROWS 8192
#define DIM   512
#define TILE  128
#define NBLK  (NROWS / TILE)                 // 64
#define NTILES (NBLK * (NBLK + 1) / 2)       // 2080
#define KSLAB 64
#define NSLAB (DIM / KSLAB)                  // 8
#define ROWPAD 144                           // bytes per smem row (128B data + 16 pad)
#define STAGE_BYTES (256 * ROWPAD)           // A(128 rows) + B(128 rows) = 36864
#define NSTAGE 2
#define SMEM_BYTES (NSTAGE * STAGE_BYTES)    // 73728  -> 2 CTAs/SM

// ---------------- device scratch ----------------
__device__ __align__(256) float          g_x [NROWS * DIM];  // normalized fp32
__device__ __align__(256) __nv_bfloat16  g_xh[NROWS * DIM];  // normalized bf16
__device__ unsigned long long            g_best[NROWS];      // packed (orderkey<<32)|idx
__device__ float                         g_log[NROWS];

__device__ __forceinline__ unsigned long long pack_vi(float v, int i) {
    unsigned u = __float_as_uint(v);
    u = (u & 0x80000000u) ? ~u : (u | 0x80000000u);
    return ((unsigned long long)u << 32) | (unsigned)i;
}
__device__ __forceinline__ uint32_t smem_u32(const void* p) {
    uint32_t a;
    asm("{ .reg .u64 t; cvta.to.shared.u64 t, %1; cvt.u32.u64 %0, t; }" : "=r"(a) : "l"(p));
    return a;
}
__device__ __forceinline__ void cpasync16(uint32_t dst, const void* src) {
    asm volatile("cp.async.cg.shared.global [%0], [%1], 16;" :: "r"(dst), "l"(src) : "memory");
}
__device__ __forceinline__ void cp_commit() { asm volatile("cp.async.commit_group;" ::: "memory"); }
__device__ __forceinline__ void ldsm4(uint32_t* r, uint32_t addr) {
    asm volatile("ldmatrix.sync.aligned.m8n8.x4.shared.b16 {%0,%1,%2,%3}, [%4];"
        : "=r"(r[0]), "=r"(r[1]), "=r"(r[2]), "=r"(r[3]) : "r"(addr));
}
__device__ __forceinline__ void mma16816(float* c, const uint32_t* a, const uint32_t* b) {
    asm volatile(
        "mma.sync.aligned.m16n8k16.row.col.f32.bf16.bf16.f32 "
        "{%0,%1,%2,%3}, {%4,%5,%6,%7}, {%8,%9}, {%0,%1,%2,%3};\n"
        : "+f"(c[0]), "+f"(c[1]), "+f"(c[2]), "+f"(c[3])
        : "r"(a[0]), "r"(a[1]), "r"(a[2]), "r"(a[3]), "r"(b[0]), "r"(b[1]));
}

// ---------------- 1) normalize rows, reset argmax buffer ----------------
__global__ void norm_kernel(const float* __restrict__ in) {
    int row = blockIdx.x;
    int tid = threadIdx.x;            // 128 threads
    if (tid == 0) g_best[row] = 0ull;
    float4 v = ((const float4*)(in + (size_t)row * DIM))[tid];
    float s = v.x*v.x + v.y*v.y + v.z*v.z + v.w*v.w;
    #pragma unroll
    for (int o = 16; o; o >>= 1) s += __shfl_xor_sync(0xffffffffu, s, o);
    __shared__ float ws[4];
    if ((tid & 31) == 0) ws[tid >> 5] = s;
    __syncthreads();
    float tot = ws[0] + ws[1] + ws[2] + ws[3];
    float inv = 1.0f / fmaxf(sqrtf(tot), 1e-8f);
    float4 o4 = make_float4(v.x*inv, v.y*inv, v.z*inv, v.w*inv);
    ((float4*)(g_x + (size_t)row * DIM))[tid] = o4;
    __nv_bfloat162* hp = (__nv_bfloat162*)(g_xh + (size_t)row * DIM);
    hp[tid*2+0] = __floats2bfloat162_rn(o4.x, o4.y);
    hp[tid*2+1] = __floats2bfloat162_rn(o4.z, o4.w);
}

// ---------------- 2) symmetric tile GEMM + dual argmax (2 CTAs/SM) ----------------
__device__ __forceinline__ void load_stage(uint32_t smb, int st, int Ibase, int Jbase, int tid) {
    const uint32_t dst0 = smb + (uint32_t)(st & (NSTAGE - 1)) * STAGE_BYTES;
    const int k0 = st * KSLAB;
    #pragma unroll
    for (int i = 0; i < 8; i++) {
        int id  = tid + i * 256;        // 0..2047
        int row = id >> 3;              // 0..255 (0-127: A rows, 128-255: B rows)
        int kc  = id & 7;               // 16B chunk within 128B k-slab row
        int gr  = (row < 128) ? (Ibase + row) : (Jbase + row - 128);
        cpasync16(dst0 + (uint32_t)row * ROWPAD + (uint32_t)kc * 16u,
                  g_xh + (size_t)gr * DIM + k0 + kc * 8);
    }
}

__global__ __launch_bounds__(256, 2) void tile_kernel() {
    extern __shared__ char smraw[];
    const uint32_t smb = smem_u32(smraw);
    const int tid  = threadIdx.x;
    const int lane = tid & 31, warp = tid >> 5;
    const int wm = warp >> 1, wn = warp & 1;       // 4x2 warp grid, 32x64 per warp
    const int lrow = lane >> 2, lk2 = (lane & 3) * 2;

    // map linear tile id -> upper-triangle block pair (I <= J)
    const int t = blockIdx.x;
    int I = 0;
    while (I + 1 <= NBLK && (I + 1) * (129 - (I + 1)) / 2 <= t) I++;
    const int J = I + (t - I * (129 - I) / 2);
    const int Ibase = I * TILE, Jbase = J * TILE;

    // prologue: slab 0 in flight
    load_stage(smb, 0, Ibase, Jbase, tid); cp_commit();

    float acc[2][8][4];
    #pragma unroll
    for (int mf = 0; mf < 2; mf++)
        #pragma unroll
        for (int nf = 0; nf < 8; nf++)
            #pragma unroll
            for (int e = 0; e < 4; e++) acc[mf][nf][e] = 0.0f;

    // ldmatrix lane addressing
    const uint32_t a_row  = (uint32_t)(wm * 32 + (lane & 15));
    const uint32_t a_koff = (uint32_t)((lane >> 4) * 16);
    const uint32_t b_row  = (uint32_t)(128 + wn * 64 + (lane & 7) + ((lane & 16) ? 8 : 0));
    const uint32_t b_koff = (uint32_t)(((lane >> 3) & 1) * 16);

    for (int s = 0; s < NSLAB; s++) {
        asm volatile("cp.async.wait_group 0;" ::: "memory");  // slab s resident
        __syncthreads();          // also: all warps done reading buffer (s+1)&1 from slab s-1
        if (s + 1 < NSLAB) {      // prefetch next slab into the other buffer
            load_stage(smb, s + 1, Ibase, Jbase, tid);
            cp_commit();
        }

        const uint32_t stg = smb + (uint32_t)(s & 1) * STAGE_BYTES;
        #pragma unroll
        for (int ks = 0; ks < 4; ks++) {
            uint32_t a[2][4], b[4][4];
            #pragma unroll
            for (int mf = 0; mf < 2; mf++)
                ldsm4(a[mf], stg + (a_row + (uint32_t)mf * 16) * ROWPAD + (uint32_t)ks * 32 + a_koff);
            #pragma unroll
            for (int p = 0; p < 4; p++)
                ldsm4(b[p], stg + (b_row + (uint32_t)p * 16) * ROWPAD + (uint32_t)ks * 32 + b_koff);
            #pragma unroll
            for (int mf = 0; mf < 2; mf++)
                #pragma unroll
                for (int p = 0; p < 4; p++) {
                    mma16816(acc[mf][2*p],     a[mf], &b[p][0]);
                    mma16816(acc[mf][2*p + 1], a[mf], &b[p][2]);
                }
        }
    }

    // ---- row argmax: rows of block I over cols of block J ----
    #pragma unroll
    for (int mf = 0; mf < 2; mf++)
        #pragma unroll
        for (int h = 0; h < 2; h++) {
            const int gr = Ibase + wm*32 + mf*16 + lrow + h*8;
            float bv = -1e30f; int bi = 0;
            #pragma unroll
            for (int nf = 0; nf < 8; nf++) {
                const int gc = Jbase + wn*64 + nf*8 + lk2;
                const float v0 = acc[mf][nf][h*2+0];
                const float v1 = acc[mf][nf][h*2+1];
                if (gc     != gr && v0 > bv) { bv = v0; bi = gc;     }
                if (gc + 1 != gr && v1 > bv) { bv = v1; bi = gc + 1; }
            }
            #pragma unroll
            for (int o = 1; o < 4; o <<= 1) {
                float ov = __shfl_xor_sync(0xffffffffu, bv, o);
                int   oi = __shfl_xor_sync(0xffffffffu, bi, o);
                if (ov > bv) { bv = ov; bi = oi; }
            }
            if ((lane & 3) == 0) atomicMax(&g_best[gr], pack_vi(bv, bi));
        }

    // ---- col argmax (symmetry): rows of block J over cols of block I ----
    if (I != J) {
        #pragma unroll
        for (int nf = 0; nf < 8; nf++)
            #pragma unroll
            for (int e = 0; e < 2; e++) {
                const int gc = Jbase + wn*64 + nf*8 + lk2 + e;
                float bv = -1e30f; int bi = 0;
                #pragma unroll
                for (int mf = 0; mf < 2; mf++)
                    #pragma unroll
                    for (int h = 0; h < 2; h++) {
                        const float v = acc[mf][nf][h*2+e];
                        if (v > bv) { bv = v; bi = Ibase + wm*32 + mf*16 + lrow + h*8; }
                    }
                #pragma unroll
                for (int o = 4; o < 32; o <<= 1) {
                    float ov = __shfl_xor_sync(0xffffffffu, bv, o);
                    int   oi = __shfl_xor_sync(0xffffffffu, bi, o);
                    if (ov > bv) { bv = ov; bi = oi; }
                }
                if (lane < 4) atomicMax(&g_best[gc], pack_vi(bv, bi));
            }
    }
}

// ---------------- 3) per-row NN distance (fp32 exact) ----------------
__global__ void dist_kernel() {
    int row = blockIdx.x;
    int tid = threadIdx.x;   // 128 threads
    int j = (int)(g_best[row] & 0xffffffffull);
    float4 a = ((const float4*)(g_x + (size_t)row * DIM))[tid];
    float4 b = ((const float4*)(g_x + (size_t)j   * DIM))[tid];
    float dx = a.x - b.x + 1e-8f;
    float dy = a.y - b.y + 1e-8f;
    float dz = a.z - b.z + 1e-8f;
    float dw = a.w - b.w + 1e-8f;
    float s = dx*dx + dy*dy + dz*dz + dw*dw;
    #pragma unroll
    for (int o = 16; o; o >>= 1) s += __shfl_xor_sync(0xffffffffu, s, o);
    __shared__ float ws[4];
    if ((tid & 31) == 0) ws[tid >> 5] = s;
    __syncthreads();
    if (tid == 0) {
        float tot = ws[0] + ws[1] + ws[2] + ws[3];
        g_log[row] = logf(sqrtf(tot) + 1e-8f);
    }
}

// ---------------- 4) deterministic final reduce ----------------
__global__ void reduce_kernel(float* __restrict__ out) {
    int tid = threadIdx.x;   // 1024 threads
    float s = 0.0f;
    #pragma unroll
    for (int i = 0; i < NROWS / 1024; i++) s += g_log[tid + i * 1024];
    #pragma unroll
    for (int o = 16; o; o >>= 1) s += __shfl_xor_sync(0xffffffffu, s, o);
    __shared__ float ws[32];
    if ((tid & 31) == 0) ws[tid >> 5] = s;
    __syncthreads();
    if (tid < 32) {
        float v = ws[tid];
        #pragma unroll
        for (int o = 16; o; o >>= 1) v += __shfl_xor_sync(0xffffffffu, v, o);
        if (tid == 0) out[0] = -v / (float)NROWS;
    }
}

extern "C" void kernel_launch(void* const* d_in, const int* in_sizes, int n_in,
                              void* d_out, int out_size) {
    const float* in = (const float*)d_in[0];
    float* out = (float*)d_out;
    (void)in_sizes; (void)n_in; (void)out_size;

    cudaFuncSetAttribute((const void*)tile_kernel,
                         cudaFuncAttributeMaxDynamicSharedMemorySize, SMEM_BYTES);

    norm_kernel<<<NROWS, 128>>>(in);
    tile_kernel<<<NTILES, 256, SMEM_BYTES>>>();
    dist_kernel<<<NROWS, 128>>>();
    reduce_kernel<<<1, 1024>>>(out);
}